// round 1
// baseline (speedup 1.0000x reference)
#include <cuda_runtime.h>
#include <math.h>

#define NCH 256

// Transposed [H, W, C] scratch for the 4 FPN levels (static device arrays —
// allocation-free per harness rules).
__device__ float g_t2[256 * 256 * NCH];   // 64 MB
__device__ float g_t3[128 * 128 * NCH];   // 16 MB
__device__ float g_t4[64 * 64 * NCH];     //  4 MB
__device__ float g_t5[32 * 32 * NCH];     //  1 MB

// [C, HW] -> [HW, C] tiled transpose. C = 256, HW multiple of 32.
__global__ __launch_bounds__(256) void transpose_chw_hwc(
    const float* __restrict__ in, float* __restrict__ out, int HW)
{
    __shared__ float tile[32][33];
    const int hw0 = blockIdx.x * 32;
    const int c0  = blockIdx.y * 32;
    const int tx = threadIdx.x, ty = threadIdx.y;
#pragma unroll
    for (int j = 0; j < 32; j += 8)
        tile[ty + j][tx] = in[(size_t)(c0 + ty + j) * HW + hw0 + tx];
    __syncthreads();
#pragma unroll
    for (int j = 0; j < 32; j += 8)
        out[(size_t)(hw0 + ty + j) * NCH + c0 + tx] = tile[tx][ty + j];
}

// One block per box. threadIdx.x = channel. Bilinear 7x7 crop from the
// routed level's transposed fmap; stage [C][49] in smem; coalesced write-out.
__global__ __launch_bounds__(256) void roi_gather(
    const float* __restrict__ boxes,
    const float* __restrict__ t2, const float* __restrict__ t3,
    const float* __restrict__ t4, const float* __restrict__ t5,
    float* __restrict__ out)
{
    extern __shared__ float sm[];  // NCH * 49 floats = 50176 B

    const int b = blockIdx.x;
    const float y1 = boxes[4 * b + 0];
    const float x1 = boxes[4 * b + 1];
    const float y2 = boxes[4 * b + 2];
    const float x2 = boxes[4 * b + 3];
    const float h = y2 - y1;
    const float w = x2 - x1;

    // roi_level = round(4 + log2(sqrt(h*w) / (224/1024))), clipped to [2,5].
    // rintf = round-half-to-even, matching jnp.round.
    const float lvl = 4.0f + log2f(sqrtf(h * w) / 0.21875f);
    int level = (int)rintf(lvl);
    level = min(5, max(2, level));

    const float* fm;
    int H;
    if      (level == 2) { fm = t2; H = 256; }
    else if (level == 3) { fm = t3; H = 128; }
    else if (level == 4) { fm = t4; H = 64;  }
    else                 { fm = t5; H = 32;  }
    const int W = H;
    const float Hm1 = (float)(H - 1);

    int   iy0[7], iy1[7], ix0[7], ix1[7];
    float lyv[7], lxv[7], vy[7], vx[7];
#pragma unroll
    for (int i = 0; i < 7; i++) {
        const float g  = (float)i / 6.0f;
        const float ys = (y1 + g * h) * Hm1;
        const float xs = (x1 + g * w) * Hm1;
        const float y0f = floorf(ys);
        const float x0f = floorf(xs);
        lyv[i] = ys - y0f;
        lxv[i] = xs - x0f;
        int y0 = min(H - 1, max(0, (int)y0f));
        int x0 = min(W - 1, max(0, (int)x0f));
        iy0[i] = y0; iy1[i] = min(H - 1, y0 + 1);
        ix0[i] = x0; ix1[i] = min(W - 1, x0 + 1);
        vy[i] = (ys >= 0.0f && ys <= Hm1) ? 1.0f : 0.0f;
        vx[i] = (xs >= 0.0f && xs <= Hm1) ? 1.0f : 0.0f;
    }

    const int c = threadIdx.x;
#pragma unroll
    for (int py = 0; py < 7; py++) {
        const float* __restrict__ r0 = fm + (size_t)iy0[py] * W * NCH;
        const float* __restrict__ r1 = fm + (size_t)iy1[py] * W * NCH;
        const float wy1v = lyv[py];
        const float wy0v = 1.0f - wy1v;
        const float vyy = vy[py];
#pragma unroll
        for (int px = 0; px < 7; px++) {
            const float f00 = r0[ix0[px] * NCH + c];
            const float f10 = r1[ix0[px] * NCH + c];
            const float f01 = r0[ix1[px] * NCH + c];
            const float f11 = r1[ix1[px] * NCH + c];
            const float wx1v = lxv[px];
            const float wx0v = 1.0f - wx1v;
            const float v = (f00 * wy0v + f10 * wy1v) * wx0v +
                            (f01 * wy0v + f11 * wy1v) * wx1v;
            sm[c * 49 + py * 7 + px] = v * (vyy * vx[px]);
        }
    }
    __syncthreads();

    float* __restrict__ ob = out + (size_t)b * (NCH * 49);
#pragma unroll 4
    for (int i = threadIdx.x; i < NCH * 49; i += 256)
        ob[i] = sm[i];
}

extern "C" void kernel_launch(void* const* d_in, const int* in_sizes, int n_in,
                              void* d_out, int out_size)
{
    const float* boxes = (const float*)d_in[0];
    const float* p2    = (const float*)d_in[1];
    const float* p3    = (const float*)d_in[2];
    const float* p4    = (const float*)d_in[3];
    const float* p5    = (const float*)d_in[4];
    float* out = (float*)d_out;

    float *t2, *t3, *t4, *t5;
    cudaGetSymbolAddress((void**)&t2, g_t2);
    cudaGetSymbolAddress((void**)&t3, g_t3);
    cudaGetSymbolAddress((void**)&t4, g_t4);
    cudaGetSymbolAddress((void**)&t5, g_t5);

    const dim3 tb(32, 8);
    transpose_chw_hwc<<<dim3((256 * 256) / 32, NCH / 32), tb>>>(p2, t2, 256 * 256);
    transpose_chw_hwc<<<dim3((128 * 128) / 32, NCH / 32), tb>>>(p3, t3, 128 * 128);
    transpose_chw_hwc<<<dim3((64 * 64) / 32, NCH / 32),   tb>>>(p4, t4, 64 * 64);
    transpose_chw_hwc<<<dim3((32 * 32) / 32, NCH / 32),   tb>>>(p5, t5, 32 * 32);

    const int nboxes = in_sizes[0] / 4;
    const size_t smem = (size_t)NCH * 49 * sizeof(float);
    cudaFuncSetAttribute(roi_gather, cudaFuncAttributeMaxDynamicSharedMemorySize, (int)smem);
    roi_gather<<<nboxes, 256, smem>>>(boxes, t2, t3, t4, t5, out);
}

// round 2
// speedup vs baseline: 1.0358x; 1.0358x over previous
#include <cuda_runtime.h>
#include <cuda_fp16.h>
#include <math.h>

#define NCH 256

// Transposed [H, W, C] fp16 scratch for the 4 FPN levels (42.5 MB total —
// fits in the 126 MB L2, so the gather reads mostly from L2).
__device__ __half g_t2[256 * 256 * NCH];   // 32 MB
__device__ __half g_t3[128 * 128 * NCH];   //  8 MB
__device__ __half g_t4[64 * 64 * NCH];     //  2 MB
__device__ __half g_t5[32 * 32 * NCH];     // 0.5 MB

// Block counts per level: (HW/32) * (NCH/32)
#define NB2 (2048 * 8)   // 16384
#define NB3 (512 * 8)    //  4096
#define NB4 (128 * 8)    //  1024
#define NB5 (32 * 8)     //   256
#define NB_TOTAL (NB2 + NB3 + NB4 + NB5)

// Fused [C, HW] -> [HW, C] transpose for all 4 levels, f32 -> f16.
__global__ __launch_bounds__(256) void transpose_all(
    const float* __restrict__ p2, const float* __restrict__ p3,
    const float* __restrict__ p4, const float* __restrict__ p5)
{
    __shared__ float tile[32][33];

    int bid = blockIdx.x;
    const float* __restrict__ in;
    __half* __restrict__ out;
    int HW;
    if (bid < NB2)                   { in = p2; out = g_t2; HW = 65536; }
    else if (bid < NB2 + NB3)        { bid -= NB2;         in = p3; out = g_t3; HW = 16384; }
    else if (bid < NB2 + NB3 + NB4)  { bid -= NB2 + NB3;   in = p4; out = g_t4; HW = 4096; }
    else                             { bid -= NB2+NB3+NB4; in = p5; out = g_t5; HW = 1024; }

    const int nhw = HW >> 5;               // HW/32 tile-columns
    const int hw0 = (bid % nhw) * 32;
    const int c0  = (bid / nhw) * 32;
    const int tx = threadIdx.x, ty = threadIdx.y;

#pragma unroll
    for (int j = 0; j < 32; j += 8)
        tile[ty + j][tx] = in[(size_t)(c0 + ty + j) * HW + hw0 + tx];
    __syncthreads();
#pragma unroll
    for (int j = 0; j < 32; j += 8)
        out[(size_t)(hw0 + ty + j) * NCH + c0 + tx] = __float2half_rn(tile[tx][ty + j]);
}

// One block per box. threadIdx.x = channel. Bilinear 7x7 crop from the routed
// level's transposed fp16 fmap; stage [C][49] fp32 in smem; coalesced write.
__global__ __launch_bounds__(256) void roi_gather(
    const float* __restrict__ boxes, float* __restrict__ out)
{
    extern __shared__ float sm[];  // NCH * 49 floats = 50176 B

    const int b = blockIdx.x;
    const float y1 = boxes[4 * b + 0];
    const float x1 = boxes[4 * b + 1];
    const float y2 = boxes[4 * b + 2];
    const float x2 = boxes[4 * b + 3];
    const float h = y2 - y1;
    const float w = x2 - x1;

    // roi_level = round(4 + log2(sqrt(h*w) / (224/1024))), clipped to [2,5].
    const float lvl = 4.0f + log2f(sqrtf(h * w) / 0.21875f);
    int level = (int)rintf(lvl);
    level = min(5, max(2, level));

    const __half* __restrict__ fm;
    int H;
    if      (level == 2) { fm = g_t2; H = 256; }
    else if (level == 3) { fm = g_t3; H = 128; }
    else if (level == 4) { fm = g_t4; H = 64;  }
    else                 { fm = g_t5; H = 32;  }
    const int W = H;
    const float Hm1 = (float)(H - 1);

    int   iy0[7], iy1[7], ix0[7], ix1[7];
    float lyv[7], lxv[7], vy[7], vx[7];
#pragma unroll
    for (int i = 0; i < 7; i++) {
        const float g  = (float)i / 6.0f;
        const float ys = (y1 + g * h) * Hm1;
        const float xs = (x1 + g * w) * Hm1;
        const float y0f = floorf(ys);
        const float x0f = floorf(xs);
        lyv[i] = ys - y0f;
        lxv[i] = xs - x0f;
        int y0 = min(H - 1, max(0, (int)y0f));
        int x0 = min(W - 1, max(0, (int)x0f));
        iy0[i] = y0; iy1[i] = min(H - 1, y0 + 1);
        ix0[i] = x0; ix1[i] = min(W - 1, x0 + 1);
        vy[i] = (ys >= 0.0f && ys <= Hm1) ? 1.0f : 0.0f;
        vx[i] = (xs >= 0.0f && xs <= Hm1) ? 1.0f : 0.0f;
    }

    const int c = threadIdx.x;
#pragma unroll
    for (int py = 0; py < 7; py++) {
        const __half* __restrict__ r0 = fm + (size_t)iy0[py] * W * NCH;
        const __half* __restrict__ r1 = fm + (size_t)iy1[py] * W * NCH;
        const float wy1v = lyv[py];
        const float wy0v = 1.0f - wy1v;
        const float vyy = vy[py];
#pragma unroll
        for (int px = 0; px < 7; px++) {
            const float f00 = __half2float(r0[ix0[px] * NCH + c]);
            const float f10 = __half2float(r1[ix0[px] * NCH + c]);
            const float f01 = __half2float(r0[ix1[px] * NCH + c]);
            const float f11 = __half2float(r1[ix1[px] * NCH + c]);
            const float wx1v = lxv[px];
            const float wx0v = 1.0f - wx1v;
            const float v = (f00 * wy0v + f10 * wy1v) * wx0v +
                            (f01 * wy0v + f11 * wy1v) * wx1v;
            sm[c * 49 + py * 7 + px] = v * (vyy * vx[px]);
        }
    }
    __syncthreads();

    float* __restrict__ ob = out + (size_t)b * (NCH * 49);
#pragma unroll 4
    for (int i = threadIdx.x; i < NCH * 49; i += 256)
        ob[i] = sm[i];
}

extern "C" void kernel_launch(void* const* d_in, const int* in_sizes, int n_in,
                              void* d_out, int out_size)
{
    const float* boxes = (const float*)d_in[0];
    const float* p2    = (const float*)d_in[1];
    const float* p3    = (const float*)d_in[2];
    const float* p4    = (const float*)d_in[3];
    const float* p5    = (const float*)d_in[4];
    float* out = (float*)d_out;

    transpose_all<<<NB_TOTAL, dim3(32, 8)>>>(p2, p3, p4, p5);

    const int nboxes = in_sizes[0] / 4;
    const size_t smem = (size_t)NCH * 49 * sizeof(float);
    cudaFuncSetAttribute(roi_gather, cudaFuncAttributeMaxDynamicSharedMemorySize, (int)smem);
    roi_gather<<<nboxes, 256, smem>>>(boxes, out);
}

// round 3
// speedup vs baseline: 1.2127x; 1.1708x over previous
#include <cuda_runtime.h>
#include <cuda_fp16.h>
#include <math.h>

#define NCH 256

// fp16 transposed [H,W,C] scratch for levels 3..5 only (10.5 MB — L2-resident).
// Level 2 (~1.4% of boxes) is gathered directly from the raw [C,H,W] p2.
__device__ __half g_t3[128 * 128 * NCH];  //  8 MB
__device__ __half g_t4[64 * 64 * NCH];    //  2 MB
__device__ __half g_t5[32 * 32 * NCH];    // 0.5 MB

// Tiles: 64 channels x 32 hw. blocks = (HW/32) * (256/64)
#define NB3T 2048
#define NB4T 512
#define NB5T 128
#define NBT  (NB3T + NB4T + NB5T)

__global__ __launch_bounds__(256) void transpose345(
    const float* __restrict__ p3, const float* __restrict__ p4,
    const float* __restrict__ p5)
{
    __shared__ float tile[64][33];

    int bid = blockIdx.x;
    const float* __restrict__ in;
    __half* __restrict__ out;
    int HW;
    if (bid < NB3T)              { in = p3; out = g_t3; HW = 16384; }
    else if (bid < NB3T + NB4T)  { bid -= NB3T;        in = p4; out = g_t4; HW = 4096; }
    else                         { bid -= NB3T + NB4T; in = p5; out = g_t5; HW = 1024; }

    const int nhw = HW >> 5;
    const int hw0 = (bid % nhw) * 32;
    const int c0  = (bid / nhw) * 64;
    const int tx = threadIdx.x, ty = threadIdx.y;

#pragma unroll
    for (int cc = ty; cc < 64; cc += 8)
        tile[cc][tx] = in[(size_t)(c0 + cc) * HW + hw0 + tx];
    __syncthreads();
    // Store: warp writes 32 half2 = 128B contiguous along C.
#pragma unroll
    for (int hh = ty; hh < 32; hh += 8) {
        __half2 v = __floats2half2_rn(tile[2 * tx][hh], tile[2 * tx + 1][hh]);
        *reinterpret_cast<__half2*>(&out[(size_t)(hw0 + hh) * NCH + c0 + 2 * tx]) = v;
    }
}

// 2 blocks per box (128 channels each). tx&127 = local channel; tx>>7 splits
// the 7 pooled rows 4/3. Stage [128][49] fp32 in smem; coalesced write-out.
__global__ __launch_bounds__(256) void roi_gather(
    const float* __restrict__ boxes, const float* __restrict__ p2,
    float* __restrict__ out)
{
    __shared__ float sm[128 * 49];  // 25088 B

    const int b    = blockIdx.x >> 1;
    const int half = blockIdx.x & 1;

    const float y1 = boxes[4 * b + 0];
    const float x1 = boxes[4 * b + 1];
    const float y2 = boxes[4 * b + 2];
    const float x2 = boxes[4 * b + 3];
    const float h = y2 - y1;
    const float w = x2 - x1;

    const float lvl = 4.0f + log2f(sqrtf(h * w) / 0.21875f);
    int level = (int)rintf(lvl);
    level = min(5, max(2, level));

    const __half* __restrict__ fm16 = g_t5;
    int H = 32;
    if      (level == 2) { H = 256; }
    else if (level == 3) { fm16 = g_t3; H = 128; }
    else if (level == 4) { fm16 = g_t4; H = 64;  }
    const int W = H;
    const float Hm1 = (float)(H - 1);

    // Precompute x sample data (shared across all py).
    int   ix0[7], ix1[7];
    float lxv[7], vx[7];
#pragma unroll
    for (int i = 0; i < 7; i++) {
        const float g  = (float)i / 6.0f;
        const float xs = (x1 + g * w) * Hm1;
        const float x0f = floorf(xs);
        lxv[i] = xs - x0f;
        int x0 = min(W - 1, max(0, (int)x0f));
        ix0[i] = x0; ix1[i] = min(W - 1, x0 + 1);
        vx[i] = (xs >= 0.0f && xs <= Hm1) ? 1.0f : 0.0f;
    }

    const int tx  = threadIdx.x;
    const int cl  = tx & 127;           // local channel 0..127
    const int c   = half * 128 + cl;    // global channel
    const int pyh = tx >> 7;            // 0 -> py 0..3, 1 -> py 4..6
    const int py_beg = pyh * 4;
    const int py_end = py_beg + 4 - pyh;

    for (int py = py_beg; py < py_end; py++) {
        const float g  = (float)py / 6.0f;
        const float ys = (y1 + g * h) * Hm1;
        const float y0f = floorf(ys);
        const float ly = ys - y0f;
        int y0 = min(H - 1, max(0, (int)y0f));
        const int iy1 = min(H - 1, y0 + 1);
        const float vy = (ys >= 0.0f && ys <= Hm1) ? 1.0f : 0.0f;
        const float wy1v = ly, wy0v = 1.0f - ly;

        if (level == 2) {
            // Direct read from raw [C, 256, 256] fp32 p2.
            const float* __restrict__ base = p2 + (size_t)c * 65536;
            const float* __restrict__ r0 = base + y0 * 256;
            const float* __restrict__ r1 = base + iy1 * 256;
#pragma unroll
            for (int px = 0; px < 7; px++) {
                const float f00 = r0[ix0[px]];
                const float f10 = r1[ix0[px]];
                const float f01 = r0[ix1[px]];
                const float f11 = r1[ix1[px]];
                const float wx1v = lxv[px], wx0v = 1.0f - wx1v;
                const float v = (f00 * wy0v + f10 * wy1v) * wx0v +
                                (f01 * wy0v + f11 * wy1v) * wx1v;
                sm[cl * 49 + py * 7 + px] = v * (vy * vx[px]);
            }
        } else {
            const __half* __restrict__ r0 = fm16 + ((size_t)y0  * W) * NCH + c;
            const __half* __restrict__ r1 = fm16 + ((size_t)iy1 * W) * NCH + c;
#pragma unroll
            for (int px = 0; px < 7; px++) {
                const float f00 = __half2float(r0[ix0[px] * NCH]);
                const float f10 = __half2float(r1[ix0[px] * NCH]);
                const float f01 = __half2float(r0[ix1[px] * NCH]);
                const float f11 = __half2float(r1[ix1[px] * NCH]);
                const float wx1v = lxv[px], wx0v = 1.0f - wx1v;
                const float v = (f00 * wy0v + f10 * wy1v) * wx0v +
                                (f01 * wy0v + f11 * wy1v) * wx1v;
                sm[cl * 49 + py * 7 + px] = v * (vy * vx[px]);
            }
        }
    }
    __syncthreads();

    float* __restrict__ ob = out + (size_t)b * (NCH * 49) + (size_t)half * (128 * 49);
#pragma unroll 4
    for (int i = tx; i < 128 * 49; i += 256)
        ob[i] = sm[i];
}

extern "C" void kernel_launch(void* const* d_in, const int* in_sizes, int n_in,
                              void* d_out, int out_size)
{
    const float* boxes = (const float*)d_in[0];
    const float* p2    = (const float*)d_in[1];
    const float* p3    = (const float*)d_in[2];
    const float* p4    = (const float*)d_in[3];
    const float* p5    = (const float*)d_in[4];
    float* out = (float*)d_out;

    transpose345<<<NBT, dim3(32, 8)>>>(p3, p4, p5);

    const int nboxes = in_sizes[0] / 4;
    roi_gather<<<2 * nboxes, 256>>>(boxes, p2, out);
}